// round 1
// baseline (speedup 1.0000x reference)
#include <cuda_runtime.h>
#include <math.h>
#include <math_constants.h>

// Problem constants
#define Bq 4
#define Sq 1024
#define Dm 1024
#define Hn 16
#define DHd 64

// Scratch (allocation-free rule: __device__ globals)
__device__ float g_qp[Bq * Sq * Dm];
__device__ float g_kp[Bq * Sq * Dm];
__device__ float g_vp[Bq * Sq * Dm];
__device__ float g_ao[Bq * Sq * Dm];

// ---------------------------------------------------------------------------
// GEMM: C[M,N] = relu(A[M,K] @ W[K,N] + bias[N])
// 128x128 block tile, BK=16, 256 threads, 8x8 per-thread micro-tile.
// M,N,K all divisible by tile dims for this problem (4096/1024/1024).
// ---------------------------------------------------------------------------
#define BM 128
#define BN 128
#define BK 16

__global__ __launch_bounds__(256) void gemm_bias_relu(
    const float* __restrict__ A, const float* __restrict__ W,
    const float* __restrict__ bias, float* __restrict__ C,
    int M, int N, int K)
{
    __shared__ float As[BK][BM + 4];   // A tile, transposed: As[k][m]
    __shared__ float Bs[BK][BN + 4];   // W tile: Bs[k][n]

    const int tid = threadIdx.x;
    const int tx = tid & 15;           // 0..15 -> n micro
    const int ty = tid >> 4;           // 0..15 -> m micro
    const int m0 = blockIdx.y * BM;
    const int n0 = blockIdx.x * BN;

    float acc[8][8];
    #pragma unroll
    for (int i = 0; i < 8; i++)
        #pragma unroll
        for (int j = 0; j < 8; j++) acc[i][j] = 0.0f;

    for (int k0 = 0; k0 < K; k0 += BK) {
        // Load A tile (128 rows x 16 cols), store transposed.
        #pragma unroll
        for (int r = 0; r < 2; r++) {
            int idx = tid + r * 256;          // 0..511 float4 slots
            int row = idx >> 2;               // 0..127
            int c4  = (idx & 3) * 4;          // 0,4,8,12
            float4 v = *(const float4*)(A + (size_t)(m0 + row) * K + k0 + c4);
            As[c4 + 0][row] = v.x;
            As[c4 + 1][row] = v.y;
            As[c4 + 2][row] = v.z;
            As[c4 + 3][row] = v.w;
        }
        // Load W tile (16 rows x 128 cols), row-major.
        #pragma unroll
        for (int r = 0; r < 2; r++) {
            int idx = tid + r * 256;          // 0..511 float4 slots
            int row = idx >> 5;               // 0..15
            int c4  = (idx & 31) * 4;         // 0..124
            float4 v = *(const float4*)(W + (size_t)(k0 + row) * N + n0 + c4);
            *(float4*)&Bs[row][c4] = v;
        }
        __syncthreads();

        #pragma unroll
        for (int kk = 0; kk < BK; kk++) {
            float a[8], b[8];
            *(float4*)&a[0] = *(const float4*)&As[kk][ty * 8];
            *(float4*)&a[4] = *(const float4*)&As[kk][ty * 8 + 4];
            *(float4*)&b[0] = *(const float4*)&Bs[kk][tx * 8];
            *(float4*)&b[4] = *(const float4*)&Bs[kk][tx * 8 + 4];
            #pragma unroll
            for (int i = 0; i < 8; i++)
                #pragma unroll
                for (int j = 0; j < 8; j++)
                    acc[i][j] = fmaf(a[i], b[j], acc[i][j]);
        }
        __syncthreads();
    }

    // Epilogue: bias + relu, vectorized store
    #pragma unroll
    for (int i = 0; i < 8; i++) {
        int row = m0 + ty * 8 + i;
        #pragma unroll
        for (int j4 = 0; j4 < 2; j4++) {
            int col = n0 + tx * 8 + j4 * 4;
            float4 o;
            o.x = fmaxf(acc[i][j4 * 4 + 0] + bias[col + 0], 0.0f);
            o.y = fmaxf(acc[i][j4 * 4 + 1] + bias[col + 1], 0.0f);
            o.z = fmaxf(acc[i][j4 * 4 + 2] + bias[col + 2], 0.0f);
            o.w = fmaxf(acc[i][j4 * 4 + 3] + bias[col + 3], 0.0f);
            *(float4*)(C + (size_t)row * N + col) = o;
        }
    }
}

// ---------------------------------------------------------------------------
// Fused flash attention (fp32, online softmax).
// Grid: (S/64, B*H). 256 threads (16x16), each owns 4x4 of the 64x64 tiles.
// smem: Qs[64][68] | Kt[64][65] (K transposed) | Vs[64][68] | Ps[64][68]
// ---------------------------------------------------------------------------
#define QS_LD 68
#define KT_LD 65
#define VS_LD 68
#define PS_LD 68
#define ATT_SMEM ((64 * QS_LD + 64 * KT_LD + 64 * VS_LD + 64 * PS_LD) * 4)

__global__ __launch_bounds__(256) void attention_fused(
    const float* __restrict__ QP, const float* __restrict__ KP,
    const float* __restrict__ VP, float* __restrict__ AO)
{
    extern __shared__ float sm[];
    float* Qs = sm;                     // [64][68] row-major
    float* Kt = Qs + 64 * QS_LD;        // [64][65] : Kt[d][j]
    float* Vs = Kt + 64 * KT_LD;        // [64][68] row-major
    float* Ps = Vs + 64 * VS_LD;        // [64][68]

    const int tid = threadIdx.x;
    const int tx = tid & 15;            // key/output-col micro (4 cols)
    const int ty = tid >> 4;            // query-row micro (4 rows)
    const int bh = blockIdx.y;
    const int b  = bh / Hn;
    const int h  = bh % Hn;
    const int q0 = blockIdx.x * 64;
    const float scale = 0.125f;         // 1/sqrt(64)

    const float* Qb = QP + ((size_t)b * Sq + q0) * Dm + h * DHd;

    // Load Q tile (64 rows x 64 head-cols)
    #pragma unroll
    for (int r = 0; r < 4; r++) {
        int idx = tid + r * 256;        // 0..1023 = 64 rows x 16 float4
        int row = idx >> 4;
        int c4  = (idx & 15) * 4;
        float4 v = *(const float4*)(Qb + (size_t)row * Dm + c4);
        *(float4*)&Qs[row * QS_LD + c4] = v;
    }

    float m_i[4], l_i[4], o[4][4];
    #pragma unroll
    for (int i = 0; i < 4; i++) {
        m_i[i] = -CUDART_INF_F;
        l_i[i] = 0.0f;
        #pragma unroll
        for (int j = 0; j < 4; j++) o[i][j] = 0.0f;
    }

    for (int t = 0; t < Sq; t += 64) {
        const float* Kb = KP + ((size_t)b * Sq + t) * Dm + h * DHd;
        const float* Vb = VP + ((size_t)b * Sq + t) * Dm + h * DHd;
        __syncthreads();  // all consumers of prev Kt/Vs/Ps done
        #pragma unroll
        for (int r = 0; r < 4; r++) {
            int idx = tid + r * 256;
            int row = idx >> 4;
            int c4  = (idx & 15) * 4;
            float4 kv = *(const float4*)(Kb + (size_t)row * Dm + c4);
            Kt[(c4 + 0) * KT_LD + row] = kv.x;
            Kt[(c4 + 1) * KT_LD + row] = kv.y;
            Kt[(c4 + 2) * KT_LD + row] = kv.z;
            Kt[(c4 + 3) * KT_LD + row] = kv.w;
            float4 vv = *(const float4*)(Vb + (size_t)row * Dm + c4);
            *(float4*)&Vs[row * VS_LD + c4] = vv;
        }
        __syncthreads();

        // scores: s[i][j] = scale * sum_d Q[ty*4+i][d] * K[tx*4+j][d]
        float s[4][4];
        #pragma unroll
        for (int i = 0; i < 4; i++)
            #pragma unroll
            for (int j = 0; j < 4; j++) s[i][j] = 0.0f;

        #pragma unroll 8
        for (int d = 0; d < 64; d++) {
            float a[4], bb[4];
            #pragma unroll
            for (int i = 0; i < 4; i++) a[i]  = Qs[(ty * 4 + i) * QS_LD + d];
            #pragma unroll
            for (int j = 0; j < 4; j++) bb[j] = Kt[d * KT_LD + tx * 4 + j];
            #pragma unroll
            for (int i = 0; i < 4; i++)
                #pragma unroll
                for (int j = 0; j < 4; j++)
                    s[i][j] = fmaf(a[i], bb[j], s[i][j]);
        }

        // online softmax per query row (rows replicated across the 16 tx lanes)
        #pragma unroll
        for (int i = 0; i < 4; i++) {
            float mx = s[i][0] * scale;
            #pragma unroll
            for (int j = 1; j < 4; j++) mx = fmaxf(mx, s[i][j] * scale);
            #pragma unroll
            for (int off = 8; off >= 1; off >>= 1)
                mx = fmaxf(mx, __shfl_xor_sync(0xffffffffu, mx, off, 16));
            float mnew = fmaxf(m_i[i], mx);
            float corr = __expf(m_i[i] - mnew);
            float rs = 0.0f;
            #pragma unroll
            for (int j = 0; j < 4; j++) {
                float p = __expf(s[i][j] * scale - mnew);
                s[i][j] = p;
                rs += p;
            }
            #pragma unroll
            for (int off = 8; off >= 1; off >>= 1)
                rs += __shfl_xor_sync(0xffffffffu, rs, off, 16);
            l_i[i] = l_i[i] * corr + rs;
            m_i[i] = mnew;
            #pragma unroll
            for (int j = 0; j < 4; j++) {
                o[i][j] *= corr;
                Ps[(ty * 4 + i) * PS_LD + tx * 4 + j] = s[i][j];
            }
        }
        __syncthreads();

        // o[i][d] += sum_j P[ty*4+i][j] * V[j][tx*4+d]
        #pragma unroll 8
        for (int j = 0; j < 64; j++) {
            float a[4], bb[4];
            #pragma unroll
            for (int i = 0; i < 4; i++) a[i]  = Ps[(ty * 4 + i) * PS_LD + j];
            #pragma unroll
            for (int d = 0; d < 4; d++) bb[d] = Vs[j * VS_LD + tx * 4 + d];
            #pragma unroll
            for (int i = 0; i < 4; i++)
                #pragma unroll
                for (int d = 0; d < 4; d++)
                    o[i][d] = fmaf(a[i], bb[d], o[i][d]);
        }
    }

    // normalize + store
    float* Ob = AO + ((size_t)b * Sq + q0) * Dm + h * DHd;
    #pragma unroll
    for (int i = 0; i < 4; i++) {
        float inv = 1.0f / l_i[i];
        float4 v;
        v.x = o[i][0] * inv;
        v.y = o[i][1] * inv;
        v.z = o[i][2] * inv;
        v.w = o[i][3] * inv;
        *(float4*)(Ob + (size_t)(ty * 4 + i) * Dm + tx * 4) = v;
    }
}

// ---------------------------------------------------------------------------
// Launcher
// Inputs (metadata order): q, k, v, Wq, bq, Wk, bk, Wv, bv, Wo, bo
// ---------------------------------------------------------------------------
extern "C" void kernel_launch(void* const* d_in, const int* in_sizes, int n_in,
                              void* d_out, int out_size)
{
    const float* q  = (const float*)d_in[0];
    const float* k  = (const float*)d_in[1];
    const float* v  = (const float*)d_in[2];
    const float* Wq = (const float*)d_in[3];
    const float* bq = (const float*)d_in[4];
    const float* Wk = (const float*)d_in[5];
    const float* bk = (const float*)d_in[6];
    const float* Wv = (const float*)d_in[7];
    const float* bv = (const float*)d_in[8];
    const float* Wo = (const float*)d_in[9];
    const float* bo = (const float*)d_in[10];
    float* out = (float*)d_out;

    float *qp, *kp, *vp, *ao;
    cudaGetSymbolAddress((void**)&qp, g_qp);
    cudaGetSymbolAddress((void**)&kp, g_kp);
    cudaGetSymbolAddress((void**)&vp, g_vp);
    cudaGetSymbolAddress((void**)&ao, g_ao);

    cudaFuncSetAttribute(attention_fused,
                         cudaFuncAttributeMaxDynamicSharedMemorySize, ATT_SMEM);

    const int M = Bq * Sq;   // 4096
    const int N = Dm;        // 1024
    const int K = Dm;        // 1024
    dim3 gGemm(N / BN, M / BM);   // (8, 32)

    gemm_bias_relu<<<gGemm, 256>>>(q, Wq, bq, qp, M, N, K);
    gemm_bias_relu<<<gGemm, 256>>>(k, Wk, bk, kp, M, N, K);
    gemm_bias_relu<<<gGemm, 256>>>(v, Wv, bv, vp, M, N, K);

    dim3 gAtt(Sq / 64, Bq * Hn);  // (16, 64)
    attention_fused<<<gAtt, 256, ATT_SMEM>>>(qp, kp, vp, ao);

    gemm_bias_relu<<<gGemm, 256>>>(ao, Wo, bo, out, M, N, K);
}

// round 2
// speedup vs baseline: 1.6349x; 1.6349x over previous
#include <cuda_runtime.h>
#include <math.h>
#include <math_constants.h>
#include <stdint.h>

// Problem constants
#define Bq 4
#define Sq 1024
#define Dm 1024
#define Hn 16
#define DHd 64

// Scratch (allocation-free rule: __device__ globals)
__device__ float g_qp[Bq * Sq * Dm];
__device__ float g_kp[Bq * Sq * Dm];
__device__ float g_vp[Bq * Sq * Dm];
__device__ float g_ao[Bq * Sq * Dm];

// ---------------------------------------------------------------------------
// tf32 tensor-core GEMM: C[M,N] = relu(A[M,K] @ W[K,N] + bias[N])
// 128x128x32 block tile, 8 warps (2x4 -> 64x32 warp tile),
// mma.sync.m16n8k8 tf32 with fp32 accumulate.
// ---------------------------------------------------------------------------
#define BM 128
#define BN 128
#define BK 32
#define AS_LD 40    // 128 rows x (32+8) floats  (float4-storable, 2-way LDS conflict)
#define BS_LD 136   // 32 rows x (128+8) floats  (conflict-free frag loads + stores)

__device__ __forceinline__ float f2tf32(float x) {
    uint32_t u;
    asm("cvt.rna.tf32.f32 %0, %1;" : "=r"(u) : "f"(x));
    return __uint_as_float(u);
}

__device__ __forceinline__ void mma_tf32(float c[4], const uint32_t a[4],
                                         const uint32_t b[2]) {
    asm volatile(
        "mma.sync.aligned.m16n8k8.row.col.f32.tf32.tf32.f32 "
        "{%0,%1,%2,%3}, {%4,%5,%6,%7}, {%8,%9}, {%0,%1,%2,%3};\n"
        : "+f"(c[0]), "+f"(c[1]), "+f"(c[2]), "+f"(c[3])
        : "r"(a[0]), "r"(a[1]), "r"(a[2]), "r"(a[3]), "r"(b[0]), "r"(b[1]));
}

__global__ __launch_bounds__(256) void gemm_tf32_bias_relu(
    const float* __restrict__ A, const float* __restrict__ W,
    const float* __restrict__ bias, float* __restrict__ C,
    int M, int N, int K)
{
    __shared__ float As[BM][AS_LD];
    __shared__ float Bs[BK][BS_LD];

    const int tid  = threadIdx.x;
    const int lane = tid & 31;
    const int warp = tid >> 5;
    const int gid  = lane >> 2;    // 0..7
    const int tig  = lane & 3;     // 0..3
    const int wm   = (warp & 1) * 64;   // warp m offset in tile
    const int wn   = (warp >> 1) * 32;  // warp n offset in tile
    const int m0   = blockIdx.y * BM;
    const int n0   = blockIdx.x * BN;

    float acc[4][4][4];
    #pragma unroll
    for (int i = 0; i < 4; i++)
        #pragma unroll
        for (int j = 0; j < 4; j++)
            #pragma unroll
            for (int r = 0; r < 4; r++) acc[i][j][r] = 0.0f;

    for (int k0 = 0; k0 < K; k0 += BK) {
        // A tile: 128 rows x 32 cols -> As[m][k] (tf32-converted)
        #pragma unroll
        for (int r = 0; r < 4; r++) {
            int idx = tid + r * 256;      // 0..1023 float4 slots
            int row = idx >> 3;           // 8 float4 per row
            int c4  = (idx & 7) * 4;
            float4 v = *(const float4*)(A + (size_t)(m0 + row) * K + k0 + c4);
            v.x = f2tf32(v.x); v.y = f2tf32(v.y);
            v.z = f2tf32(v.z); v.w = f2tf32(v.w);
            *(float4*)&As[row][c4] = v;
        }
        // B tile: 32 rows x 128 cols -> Bs[k][n] (tf32-converted)
        #pragma unroll
        for (int r = 0; r < 4; r++) {
            int idx = tid + r * 256;
            int row = idx >> 5;           // 32 float4 per row
            int c4  = (idx & 31) * 4;
            float4 v = *(const float4*)(W + (size_t)(k0 + row) * N + n0 + c4);
            v.x = f2tf32(v.x); v.y = f2tf32(v.y);
            v.z = f2tf32(v.z); v.w = f2tf32(v.w);
            *(float4*)&Bs[row][c4] = v;
        }
        __syncthreads();

        #pragma unroll
        for (int kk = 0; kk < BK; kk += 8) {
            uint32_t aF[4][4], bF[4][2];
            #pragma unroll
            for (int i = 0; i < 4; i++) {
                int mr = wm + i * 16 + gid;
                aF[i][0] = __float_as_uint(As[mr    ][kk + tig    ]);
                aF[i][1] = __float_as_uint(As[mr + 8][kk + tig    ]);
                aF[i][2] = __float_as_uint(As[mr    ][kk + tig + 4]);
                aF[i][3] = __float_as_uint(As[mr + 8][kk + tig + 4]);
            }
            #pragma unroll
            for (int j = 0; j < 4; j++) {
                int nc = wn + j * 8 + gid;
                bF[j][0] = __float_as_uint(Bs[kk + tig    ][nc]);
                bF[j][1] = __float_as_uint(Bs[kk + tig + 4][nc]);
            }
            #pragma unroll
            for (int i = 0; i < 4; i++)
                #pragma unroll
                for (int j = 0; j < 4; j++)
                    mma_tf32(acc[i][j], aF[i], bF[j]);
        }
        __syncthreads();
    }

    // Epilogue: bias + relu.
    // c0:(g,2t) c1:(g,2t+1) c2:(g+8,2t) c3:(g+8,2t+1)
    #pragma unroll
    for (int i = 0; i < 4; i++) {
        int r0 = m0 + wm + i * 16 + gid;
        #pragma unroll
        for (int j = 0; j < 4; j++) {
            int col = n0 + wn + j * 8 + tig * 2;
            float bb0 = bias[col], bb1 = bias[col + 1];
            float2 v0, v1;
            v0.x = fmaxf(acc[i][j][0] + bb0, 0.0f);
            v0.y = fmaxf(acc[i][j][1] + bb1, 0.0f);
            v1.x = fmaxf(acc[i][j][2] + bb0, 0.0f);
            v1.y = fmaxf(acc[i][j][3] + bb1, 0.0f);
            *(float2*)(C + (size_t)r0 * N + col) = v0;
            *(float2*)(C + (size_t)(r0 + 8) * N + col) = v1;
        }
    }
}

// ---------------------------------------------------------------------------
// Fused flash attention (fp32, online softmax) — unchanged from Round 1.
// ---------------------------------------------------------------------------
#define QS_LD 68
#define KT_LD 65
#define VS_LD 68
#define PS_LD 68
#define ATT_SMEM ((64 * QS_LD + 64 * KT_LD + 64 * VS_LD + 64 * PS_LD) * 4)

__global__ __launch_bounds__(256) void attention_fused(
    const float* __restrict__ QP, const float* __restrict__ KP,
    const float* __restrict__ VP, float* __restrict__ AO)
{
    extern __shared__ float sm[];
    float* Qs = sm;
    float* Kt = Qs + 64 * QS_LD;
    float* Vs = Kt + 64 * KT_LD;
    float* Ps = Vs + 64 * VS_LD;

    const int tid = threadIdx.x;
    const int tx = tid & 15;
    const int ty = tid >> 4;
    const int bh = blockIdx.y;
    const int b  = bh / Hn;
    const int h  = bh % Hn;
    const int q0 = blockIdx.x * 64;
    const float scale = 0.125f;

    const float* Qb = QP + ((size_t)b * Sq + q0) * Dm + h * DHd;

    #pragma unroll
    for (int r = 0; r < 4; r++) {
        int idx = tid + r * 256;
        int row = idx >> 4;
        int c4  = (idx & 15) * 4;
        float4 v = *(const float4*)(Qb + (size_t)row * Dm + c4);
        *(float4*)&Qs[row * QS_LD + c4] = v;
    }

    float m_i[4], l_i[4], o[4][4];
    #pragma unroll
    for (int i = 0; i < 4; i++) {
        m_i[i] = -CUDART_INF_F;
        l_i[i] = 0.0f;
        #pragma unroll
        for (int j = 0; j < 4; j++) o[i][j] = 0.0f;
    }

    for (int t = 0; t < Sq; t += 64) {
        const float* Kb = KP + ((size_t)b * Sq + t) * Dm + h * DHd;
        const float* Vb = VP + ((size_t)b * Sq + t) * Dm + h * DHd;
        __syncthreads();
        #pragma unroll
        for (int r = 0; r < 4; r++) {
            int idx = tid + r * 256;
            int row = idx >> 4;
            int c4  = (idx & 15) * 4;
            float4 kv = *(const float4*)(Kb + (size_t)row * Dm + c4);
            Kt[(c4 + 0) * KT_LD + row] = kv.x;
            Kt[(c4 + 1) * KT_LD + row] = kv.y;
            Kt[(c4 + 2) * KT_LD + row] = kv.z;
            Kt[(c4 + 3) * KT_LD + row] = kv.w;
            float4 vv = *(const float4*)(Vb + (size_t)row * Dm + c4);
            *(float4*)&Vs[row * VS_LD + c4] = vv;
        }
        __syncthreads();

        float s[4][4];
        #pragma unroll
        for (int i = 0; i < 4; i++)
            #pragma unroll
            for (int j = 0; j < 4; j++) s[i][j] = 0.0f;

        #pragma unroll 8
        for (int d = 0; d < 64; d++) {
            float a[4], bb[4];
            #pragma unroll
            for (int i = 0; i < 4; i++) a[i]  = Qs[(ty * 4 + i) * QS_LD + d];
            #pragma unroll
            for (int j = 0; j < 4; j++) bb[j] = Kt[d * KT_LD + tx * 4 + j];
            #pragma unroll
            for (int i = 0; i < 4; i++)
                #pragma unroll
                for (int j = 0; j < 4; j++)
                    s[i][j] = fmaf(a[i], bb[j], s[i][j]);
        }

        #pragma unroll
        for (int i = 0; i < 4; i++) {
            float mx = s[i][0] * scale;
            #pragma unroll
            for (int j = 1; j < 4; j++) mx = fmaxf(mx, s[i][j] * scale);
            #pragma unroll
            for (int off = 8; off >= 1; off >>= 1)
                mx = fmaxf(mx, __shfl_xor_sync(0xffffffffu, mx, off, 16));
            float mnew = fmaxf(m_i[i], mx);
            float corr = __expf(m_i[i] - mnew);
            float rs = 0.0f;
            #pragma unroll
            for (int j = 0; j < 4; j++) {
                float p = __expf(s[i][j] * scale - mnew);
                s[i][j] = p;
                rs += p;
            }
            #pragma unroll
            for (int off = 8; off >= 1; off >>= 1)
                rs += __shfl_xor_sync(0xffffffffu, rs, off, 16);
            l_i[i] = l_i[i] * corr + rs;
            m_i[i] = mnew;
            #pragma unroll
            for (int j = 0; j < 4; j++) {
                o[i][j] *= corr;
                Ps[(ty * 4 + i) * PS_LD + tx * 4 + j] = s[i][j];
            }
        }
        __syncthreads();

        #pragma unroll 8
        for (int j = 0; j < 64; j++) {
            float a[4], bb[4];
            #pragma unroll
            for (int i = 0; i < 4; i++) a[i]  = Ps[(ty * 4 + i) * PS_LD + j];
            #pragma unroll
            for (int d = 0; d < 4; d++) bb[d] = Vs[j * VS_LD + tx * 4 + d];
            #pragma unroll
            for (int i = 0; i < 4; i++)
                #pragma unroll
                for (int d = 0; d < 4; d++)
                    o[i][d] = fmaf(a[i], bb[d], o[i][d]);
        }
    }

    float* Ob = AO + ((size_t)b * Sq + q0) * Dm + h * DHd;
    #pragma unroll
    for (int i = 0; i < 4; i++) {
        float inv = 1.0f / l_i[i];
        float4 v;
        v.x = o[i][0] * inv;
        v.y = o[i][1] * inv;
        v.z = o[i][2] * inv;
        v.w = o[i][3] * inv;
        *(float4*)(Ob + (size_t)(ty * 4 + i) * Dm + tx * 4) = v;
    }
}

// ---------------------------------------------------------------------------
// Launcher
// ---------------------------------------------------------------------------
extern "C" void kernel_launch(void* const* d_in, const int* in_sizes, int n_in,
                              void* d_out, int out_size)
{
    const float* q  = (const float*)d_in[0];
    const float* k  = (const float*)d_in[1];
    const float* v  = (const float*)d_in[2];
    const float* Wq = (const float*)d_in[3];
    const float* bq = (const float*)d_in[4];
    const float* Wk = (const float*)d_in[5];
    const float* bk = (const float*)d_in[6];
    const float* Wv = (const float*)d_in[7];
    const float* bv = (const float*)d_in[8];
    const float* Wo = (const float*)d_in[9];
    const float* bo = (const float*)d_in[10];
    float* out = (float*)d_out;

    float *qp, *kp, *vp, *ao;
    cudaGetSymbolAddress((void**)&qp, g_qp);
    cudaGetSymbolAddress((void**)&kp, g_kp);
    cudaGetSymbolAddress((void**)&vp, g_vp);
    cudaGetSymbolAddress((void**)&ao, g_ao);

    cudaFuncSetAttribute(attention_fused,
                         cudaFuncAttributeMaxDynamicSharedMemorySize, ATT_SMEM);

    const int M = Bq * Sq;   // 4096
    const int N = Dm;        // 1024
    const int K = Dm;        // 1024
    dim3 gGemm(N / BN, M / BM);   // (8, 32)

    gemm_tf32_bias_relu<<<gGemm, 256>>>(q, Wq, bq, qp, M, N, K);
    gemm_tf32_bias_relu<<<gGemm, 256>>>(k, Wk, bk, kp, M, N, K);
    gemm_tf32_bias_relu<<<gGemm, 256>>>(v, Wv, bv, vp, M, N, K);

    dim3 gAtt(Sq / 64, Bq * Hn);  // (16, 64)
    attention_fused<<<gAtt, 256, ATT_SMEM>>>(qp, kp, vp, ao);

    gemm_tf32_bias_relu<<<gGemm, 256>>>(ao, Wo, bo, out, M, N, K);
}

// round 3
// speedup vs baseline: 2.7690x; 1.6937x over previous
#include <cuda_runtime.h>
#include <math.h>
#include <math_constants.h>
#include <stdint.h>

// Problem constants
#define Bq 4
#define Sq 1024
#define Dm 1024
#define Hn 16
#define DHd 64

// Scratch (allocation-free rule: __device__ globals)
__device__ float g_qp[Bq * Sq * Dm];
__device__ float g_kp[Bq * Sq * Dm];
__device__ float g_vp[Bq * Sq * Dm];
__device__ float g_ao[Bq * Sq * Dm];

__device__ __forceinline__ float f2tf32(float x) {
    uint32_t u;
    asm("cvt.rna.tf32.f32 %0, %1;" : "=r"(u) : "f"(x));
    return __uint_as_float(u);
}
__device__ __forceinline__ uint32_t f2tf32u(float x) {
    uint32_t u;
    asm("cvt.rna.tf32.f32 %0, %1;" : "=r"(u) : "f"(x));
    return u;
}

__device__ __forceinline__ void mma_tf32(float c[4], const uint32_t a[4],
                                         const uint32_t b[2]) {
    asm volatile(
        "mma.sync.aligned.m16n8k8.row.col.f32.tf32.tf32.f32 "
        "{%0,%1,%2,%3}, {%4,%5,%6,%7}, {%8,%9}, {%0,%1,%2,%3};\n"
        : "+f"(c[0]), "+f"(c[1]), "+f"(c[2]), "+f"(c[3])
        : "r"(a[0]), "r"(a[1]), "r"(a[2]), "r"(a[3]), "r"(b[0]), "r"(b[1]));
}

// ---------------------------------------------------------------------------
// tf32 tensor-core GEMM: C[M,N] = relu(A[M,K] @ W[K,N] + bias[N])
// (unchanged from Round 2 — validated, ~114 TF/s)
// ---------------------------------------------------------------------------
#define BM 128
#define BN 128
#define BK 32
#define AS_LD 40
#define BS_LD 136

__global__ __launch_bounds__(256) void gemm_tf32_bias_relu(
    const float* __restrict__ A, const float* __restrict__ W,
    const float* __restrict__ bias, float* __restrict__ C,
    int M, int N, int K)
{
    __shared__ float As[BM][AS_LD];
    __shared__ float Bs[BK][BS_LD];

    const int tid  = threadIdx.x;
    const int lane = tid & 31;
    const int warp = tid >> 5;
    const int gid  = lane >> 2;
    const int tig  = lane & 3;
    const int wm   = (warp & 1) * 64;
    const int wn   = (warp >> 1) * 32;
    const int m0   = blockIdx.y * BM;
    const int n0   = blockIdx.x * BN;

    float acc[4][4][4];
    #pragma unroll
    for (int i = 0; i < 4; i++)
        #pragma unroll
        for (int j = 0; j < 4; j++)
            #pragma unroll
            for (int r = 0; r < 4; r++) acc[i][j][r] = 0.0f;

    for (int k0 = 0; k0 < K; k0 += BK) {
        #pragma unroll
        for (int r = 0; r < 4; r++) {
            int idx = tid + r * 256;
            int row = idx >> 3;
            int c4  = (idx & 7) * 4;
            float4 v = *(const float4*)(A + (size_t)(m0 + row) * K + k0 + c4);
            v.x = f2tf32(v.x); v.y = f2tf32(v.y);
            v.z = f2tf32(v.z); v.w = f2tf32(v.w);
            *(float4*)&As[row][c4] = v;
        }
        #pragma unroll
        for (int r = 0; r < 4; r++) {
            int idx = tid + r * 256;
            int row = idx >> 5;
            int c4  = (idx & 31) * 4;
            float4 v = *(const float4*)(W + (size_t)(k0 + row) * N + n0 + c4);
            v.x = f2tf32(v.x); v.y = f2tf32(v.y);
            v.z = f2tf32(v.z); v.w = f2tf32(v.w);
            *(float4*)&Bs[row][c4] = v;
        }
        __syncthreads();

        #pragma unroll
        for (int kk = 0; kk < BK; kk += 8) {
            uint32_t aF[4][4], bF[4][2];
            #pragma unroll
            for (int i = 0; i < 4; i++) {
                int mr = wm + i * 16 + gid;
                aF[i][0] = __float_as_uint(As[mr    ][kk + tig    ]);
                aF[i][1] = __float_as_uint(As[mr + 8][kk + tig    ]);
                aF[i][2] = __float_as_uint(As[mr    ][kk + tig + 4]);
                aF[i][3] = __float_as_uint(As[mr + 8][kk + tig + 4]);
            }
            #pragma unroll
            for (int j = 0; j < 4; j++) {
                int nc = wn + j * 8 + gid;
                bF[j][0] = __float_as_uint(Bs[kk + tig    ][nc]);
                bF[j][1] = __float_as_uint(Bs[kk + tig + 4][nc]);
            }
            #pragma unroll
            for (int i = 0; i < 4; i++)
                #pragma unroll
                for (int j = 0; j < 4; j++)
                    mma_tf32(acc[i][j], aF[i], bF[j]);
        }
        __syncthreads();
    }

    #pragma unroll
    for (int i = 0; i < 4; i++) {
        int r0 = m0 + wm + i * 16 + gid;
        #pragma unroll
        for (int j = 0; j < 4; j++) {
            int col = n0 + wn + j * 8 + tig * 2;
            float bb0 = bias[col], bb1 = bias[col + 1];
            float2 v0, v1;
            v0.x = fmaxf(acc[i][j][0] + bb0, 0.0f);
            v0.y = fmaxf(acc[i][j][1] + bb1, 0.0f);
            v1.x = fmaxf(acc[i][j][2] + bb0, 0.0f);
            v1.y = fmaxf(acc[i][j][3] + bb1, 0.0f);
            *(float2*)(C + (size_t)r0 * N + col) = v0;
            *(float2*)(C + (size_t)(r0 + 8) * N + col) = v1;
        }
    }
}

// ---------------------------------------------------------------------------
// Tensor-core flash attention (tf32 mma, fp32 softmax/accum).
// Block: 128 threads (4 warps), 64 query rows; each warp owns 16 rows.
// Grid: (S/64, B*H). smem: Qs/Ps[64][68] (aliased) | Ks[64][68] | Vs[64][72]
// ---------------------------------------------------------------------------
#define AQ_LD 68
#define AK_LD 68
#define AV_LD 72
#define ATT_SMEM ((64 * AQ_LD + 64 * AK_LD + 64 * AV_LD) * 4)

__global__ __launch_bounds__(128) void attention_tc(
    const float* __restrict__ QP, const float* __restrict__ KP,
    const float* __restrict__ VP, float* __restrict__ AO)
{
    extern __shared__ float sm[];
    float* Qs = sm;                  // [64][68]; reused as P buffer in loop
    float* Ks = sm + 64 * AQ_LD;     // [64][68]
    float* Vs = Ks + 64 * AK_LD;     // [64][72]

    const int tid  = threadIdx.x;
    const int lane = tid & 31;
    const int warp = tid >> 5;       // 0..3
    const int gid  = lane >> 2;      // 0..7
    const int tig  = lane & 3;       // 0..3
    const int bh   = blockIdx.y;
    const int b    = bh / Hn;
    const int h    = bh % Hn;
    const int q0   = blockIdx.x * 64;

    // Stage Q tile (64 rows x 64 dh), tf32-converted
    const float* Qb = QP + ((size_t)b * Sq + q0) * Dm + h * DHd;
    #pragma unroll
    for (int r = 0; r < 8; r++) {
        int idx = tid + r * 128;         // 0..1023 float4 slots
        int row = idx >> 4;
        int c4  = (idx & 15) * 4;
        float4 v = *(const float4*)(Qb + (size_t)row * Dm + c4);
        v.x = f2tf32(v.x); v.y = f2tf32(v.y);
        v.z = f2tf32(v.z); v.w = f2tf32(v.w);
        *(float4*)&Qs[row * AQ_LD + c4] = v;
    }
    __syncthreads();

    // Warp-local row indices (within the 64-row block)
    const int r0 = warp * 16 + gid;
    const int r1 = r0 + 8;

    // Q A-fragments, register-resident for the whole kernel
    uint32_t qF[8][4];
    #pragma unroll
    for (int kk = 0; kk < 8; kk++) {
        qF[kk][0] = __float_as_uint(Qs[r0 * AQ_LD + kk * 8 + tig    ]);
        qF[kk][1] = __float_as_uint(Qs[r1 * AQ_LD + kk * 8 + tig    ]);
        qF[kk][2] = __float_as_uint(Qs[r0 * AQ_LD + kk * 8 + tig + 4]);
        qF[kk][3] = __float_as_uint(Qs[r1 * AQ_LD + kk * 8 + tig + 4]);
    }
    // (Qs rows are partitioned per-warp for P reuse; no extra sync needed —
    //  warp w only rewrites rows [16w,16w+16) which only warp w read above.)

    float m0v = -CUDART_INF_F, m1v = -CUDART_INF_F;
    float l0 = 0.0f, l1 = 0.0f;
    float oF[8][4];
    #pragma unroll
    for (int nn = 0; nn < 8; nn++)
        #pragma unroll
        for (int r = 0; r < 4; r++) oF[nn][r] = 0.0f;

    for (int t = 0; t < Sq; t += 64) {
        // Stage K and V tiles (tf32-converted)
        const float* Kb = KP + ((size_t)b * Sq + t) * Dm + h * DHd;
        const float* Vb = VP + ((size_t)b * Sq + t) * Dm + h * DHd;
        #pragma unroll
        for (int r = 0; r < 8; r++) {
            int idx = tid + r * 128;
            int row = idx >> 4;
            int c4  = (idx & 15) * 4;
            float4 kv = *(const float4*)(Kb + (size_t)row * Dm + c4);
            kv.x = f2tf32(kv.x); kv.y = f2tf32(kv.y);
            kv.z = f2tf32(kv.z); kv.w = f2tf32(kv.w);
            *(float4*)&Ks[row * AK_LD + c4] = kv;
            float4 vv = *(const float4*)(Vb + (size_t)row * Dm + c4);
            vv.x = f2tf32(vv.x); vv.y = f2tf32(vv.y);
            vv.z = f2tf32(vv.z); vv.w = f2tf32(vv.w);
            *(float4*)&Vs[row * AV_LD + c4] = vv;
        }
        __syncthreads();

        // S = Q @ K^T   (16 rows x 64 keys per warp)
        float sF[8][4];
        #pragma unroll
        for (int nn = 0; nn < 8; nn++)
            #pragma unroll
            for (int r = 0; r < 4; r++) sF[nn][r] = 0.0f;

        #pragma unroll
        for (int kk = 0; kk < 8; kk++) {
            #pragma unroll
            for (int nn = 0; nn < 8; nn++) {
                uint32_t bK[2];
                bK[0] = __float_as_uint(Ks[(nn * 8 + gid) * AK_LD + kk * 8 + tig    ]);
                bK[1] = __float_as_uint(Ks[(nn * 8 + gid) * AK_LD + kk * 8 + tig + 4]);
                mma_tf32(sF[nn], qF[kk], bK);
            }
        }

        // scale + online softmax (rows r0: c0/c1, r1: c2/c3)
        float mx0 = -CUDART_INF_F, mx1 = -CUDART_INF_F;
        #pragma unroll
        for (int nn = 0; nn < 8; nn++) {
            sF[nn][0] *= 0.125f; sF[nn][1] *= 0.125f;
            sF[nn][2] *= 0.125f; sF[nn][3] *= 0.125f;
            mx0 = fmaxf(mx0, fmaxf(sF[nn][0], sF[nn][1]));
            mx1 = fmaxf(mx1, fmaxf(sF[nn][2], sF[nn][3]));
        }
        mx0 = fmaxf(mx0, __shfl_xor_sync(0xffffffffu, mx0, 1));
        mx0 = fmaxf(mx0, __shfl_xor_sync(0xffffffffu, mx0, 2));
        mx1 = fmaxf(mx1, __shfl_xor_sync(0xffffffffu, mx1, 1));
        mx1 = fmaxf(mx1, __shfl_xor_sync(0xffffffffu, mx1, 2));

        float mn0 = fmaxf(m0v, mx0);
        float mn1 = fmaxf(m1v, mx1);
        float corr0 = __expf(m0v - mn0);
        float corr1 = __expf(m1v - mn1);

        float rs0 = 0.0f, rs1 = 0.0f;
        #pragma unroll
        for (int nn = 0; nn < 8; nn++) {
            sF[nn][0] = __expf(sF[nn][0] - mn0);
            sF[nn][1] = __expf(sF[nn][1] - mn0);
            sF[nn][2] = __expf(sF[nn][2] - mn1);
            sF[nn][3] = __expf(sF[nn][3] - mn1);
            rs0 += sF[nn][0] + sF[nn][1];
            rs1 += sF[nn][2] + sF[nn][3];
        }
        rs0 += __shfl_xor_sync(0xffffffffu, rs0, 1);
        rs0 += __shfl_xor_sync(0xffffffffu, rs0, 2);
        rs1 += __shfl_xor_sync(0xffffffffu, rs1, 1);
        rs1 += __shfl_xor_sync(0xffffffffu, rs1, 2);

        l0 = l0 * corr0 + rs0;  m0v = mn0;
        l1 = l1 * corr1 + rs1;  m1v = mn1;

        #pragma unroll
        for (int nn = 0; nn < 8; nn++) {
            oF[nn][0] *= corr0; oF[nn][1] *= corr0;
            oF[nn][2] *= corr1; oF[nn][3] *= corr1;
        }

        // P: acc layout -> A-frag layout via per-warp smem (alias of Qs rows)
        #pragma unroll
        for (int nn = 0; nn < 8; nn++) {
            float2 v0, v1;
            v0.x = f2tf32(sF[nn][0]); v0.y = f2tf32(sF[nn][1]);
            v1.x = f2tf32(sF[nn][2]); v1.y = f2tf32(sF[nn][3]);
            *(float2*)&Qs[r0 * AQ_LD + nn * 8 + 2 * tig] = v0;
            *(float2*)&Qs[r1 * AQ_LD + nn * 8 + 2 * tig] = v1;
        }
        __syncwarp();

        uint32_t pF[8][4];
        #pragma unroll
        for (int kk = 0; kk < 8; kk++) {
            pF[kk][0] = __float_as_uint(Qs[r0 * AQ_LD + kk * 8 + tig    ]);
            pF[kk][1] = __float_as_uint(Qs[r1 * AQ_LD + kk * 8 + tig    ]);
            pF[kk][2] = __float_as_uint(Qs[r0 * AQ_LD + kk * 8 + tig + 4]);
            pF[kk][3] = __float_as_uint(Qs[r1 * AQ_LD + kk * 8 + tig + 4]);
        }

        // O += P @ V
        #pragma unroll
        for (int kk = 0; kk < 8; kk++) {
            #pragma unroll
            for (int nn = 0; nn < 8; nn++) {
                uint32_t bV[2];
                bV[0] = __float_as_uint(Vs[(kk * 8 + tig    ) * AV_LD + nn * 8 + gid]);
                bV[1] = __float_as_uint(Vs[(kk * 8 + tig + 4) * AV_LD + nn * 8 + gid]);
                mma_tf32(oF[nn], pF[kk], bV);
            }
        }
        __syncthreads();   // protect Ks/Vs before next tile's staging
    }

    // Normalize + store
    const float inv0 = 1.0f / l0;
    const float inv1 = 1.0f / l1;
    float* Ob = AO + ((size_t)b * Sq + q0) * Dm + h * DHd;
    #pragma unroll
    for (int nn = 0; nn < 8; nn++) {
        int col = nn * 8 + 2 * tig;
        float2 v0, v1;
        v0.x = oF[nn][0] * inv0; v0.y = oF[nn][1] * inv0;
        v1.x = oF[nn][2] * inv1; v1.y = oF[nn][3] * inv1;
        *(float2*)(Ob + (size_t)r0 * Dm + col) = v0;
        *(float2*)(Ob + (size_t)r1 * Dm + col) = v1;
    }
}

// ---------------------------------------------------------------------------
// Launcher
// ---------------------------------------------------------------------------
extern "C" void kernel_launch(void* const* d_in, const int* in_sizes, int n_in,
                              void* d_out, int out_size)
{
    const float* q  = (const float*)d_in[0];
    const float* k  = (const float*)d_in[1];
    const float* v  = (const float*)d_in[2];
    const float* Wq = (const float*)d_in[3];
    const float* bq = (const float*)d_in[4];
    const float* Wk = (const float*)d_in[5];
    const float* bk = (const float*)d_in[6];
    const float* Wv = (const float*)d_in[7];
    const float* bv = (const float*)d_in[8];
    const float* Wo = (const float*)d_in[9];
    const float* bo = (const float*)d_in[10];
    float* out = (float*)d_out;

    float *qp, *kp, *vp, *ao;
    cudaGetSymbolAddress((void**)&qp, g_qp);
    cudaGetSymbolAddress((void**)&kp, g_kp);
    cudaGetSymbolAddress((void**)&vp, g_vp);
    cudaGetSymbolAddress((void**)&ao, g_ao);

    cudaFuncSetAttribute(attention_tc,
                         cudaFuncAttributeMaxDynamicSharedMemorySize, ATT_SMEM);

    const int M = Bq * Sq;   // 4096
    const int N = Dm;        // 1024
    const int K = Dm;        // 1024
    dim3 gGemm(N / BN, M / BM);   // (8, 32)

    gemm_tf32_bias_relu<<<gGemm, 256>>>(q, Wq, bq, qp, M, N, K);
    gemm_tf32_bias_relu<<<gGemm, 256>>>(k, Wk, bk, kp, M, N, K);
    gemm_tf32_bias_relu<<<gGemm, 256>>>(v, Wv, bv, vp, M, N, K);

    dim3 gAtt(Sq / 64, Bq * Hn);  // (16, 64)
    attention_tc<<<gAtt, 128, ATT_SMEM>>>(qp, kp, vp, ao);

    gemm_tf32_bias_relu<<<gGemm, 256>>>(ao, Wo, bo, out, M, N, K);
}